// round 1
// baseline (speedup 1.0000x reference)
#include <cuda_runtime.h>
#include <math.h>

#define BB 128
#define TDIM 512
#define DIN 12
#define HH 64
#define DOUT 320
#define BT (BB*TDIM)

// ---------------- static scratch (no allocs allowed) ----------------
__device__ float g_b64_a[BB*HH*TDIM];
__device__ float g_b64_b[BB*HH*TDIM];
__device__ float g_b64_c[BB*HH*TDIM];
__device__ float g_b320_a[BB*DOUT*TDIM];
__device__ float g_b320_b[BB*DOUT*TDIM];
__device__ float g_b320_c[BB*DOUT*TDIM];
__device__ float g_interp[BT*DIN];
__device__ float g_wT_c01[HH*3*HH];
__device__ float g_wT_c02[HH*3*HH];
__device__ float g_wT_c1p[HH*1*DOUT];
__device__ float g_wT_c11[HH*3*DOUT];
__device__ float g_wT_c12[DOUT*3*DOUT];
__device__ float g_M12[144];
__device__ float g_c12[12];

// ---------------- small kernels ----------------
__device__ __forceinline__ float gelu1(float x) {
    return 0.5f * x * (1.0f + erff(x * 0.7071067811865476f));
}

__global__ void gelu4_kernel(const float4* __restrict__ in, float4* __restrict__ out, int n4) {
    int i = blockIdx.x * blockDim.x + threadIdx.x;
    if (i < n4) {
        float4 v = in[i];
        v.x = gelu1(v.x); v.y = gelu1(v.y); v.z = gelu1(v.z); v.w = gelu1(v.w);
        out[i] = v;
    }
}

// w[co][ci][k] -> wT[ci*K+k][co]
__global__ void repack_w_kernel(const float* __restrict__ w, float* __restrict__ wT,
                                int COUT, int CIN, int KS) {
    int n = COUT * CIN * KS;
    for (int i = blockIdx.x * blockDim.x + threadIdx.x; i < n; i += gridDim.x * blockDim.x) {
        int k = i % KS;
        int ci = (i / KS) % CIN;
        int co = i / (KS * CIN);
        wT[(ci * KS + k) * COUT + co] = w[i];
    }
}

// M12 = fc_w @ fcr_w  (12x12), c12 = fc_b @ fcr_w + fcr_b
__global__ void m12_kernel(const float* __restrict__ fc_w, const float* __restrict__ fc_b,
                           const float* __restrict__ fcr_w, const float* __restrict__ fcr_b,
                           float* __restrict__ M12, float* __restrict__ c12) {
    int tid = threadIdx.x;
    if (tid < 144) {
        int i = tid / 12, j = tid % 12;
        float s = 0.f;
        for (int k = 0; k < DOUT; k++) s += fc_w[i * DOUT + k] * fcr_w[k * 12 + j];
        M12[tid] = s;
    } else if (tid < 156) {
        int j = tid - 144;
        float s = fcr_b[j];
        for (int k = 0; k < DOUT; k++) s += fc_b[k] * fcr_w[k * 12 + j];
        c12[j] = s;
    }
}

// input projection: x[B,T,12] @ w_in[12,64] + b_in -> out[B,64,T]
__global__ void proj_in_kernel(const float* __restrict__ x, const float* __restrict__ w,
                               const float* __restrict__ bi, float* __restrict__ out) {
    int b = blockIdx.y;
    int t = blockIdx.x * 128 + threadIdx.x;
    float xv[DIN];
#pragma unroll
    for (int i = 0; i < DIN; i++) xv[i] = x[(b * TDIM + t) * DIN + i];
    for (int c = 0; c < HH; c++) {
        float s = bi[c];
#pragma unroll
        for (int i = 0; i < DIN; i++) s += xv[i] * w[i * HH + c];
        out[(b * HH + c) * TDIM + t] = s;
    }
}

// ---------------- conv (k3 dilated / 1x1), channel-major ----------------
// in [B,CIN,T], wT [CIN*KS][COUT], out [B,COUT,T]; optional residual add.
template<int CIN, int COUT, int KS, int DIL, bool RES>
__global__ __launch_bounds__(256) void conv_kernel(
    const float* __restrict__ in, const float* __restrict__ wT,
    const float* __restrict__ bias, const float* __restrict__ res,
    float* __restrict__ out)
{
    constexpr int TTILE = 128, CT = 64, CK = 16;
    constexpr int HALO = (KS / 2) * DIL;
    constexpr int WROW = TTILE + 2 * HALO;

    __shared__ float sIn[CK][WROW];
    __shared__ float sW[CK * KS][CT];

    int b   = blockIdx.z;
    int t0  = blockIdx.x * TTILE;
    int co0 = blockIdx.y * CT;
    int tid = threadIdx.x;
    int tx = tid & 31, ty = tid >> 5;

    float acc[8][4];
#pragma unroll
    for (int a = 0; a < 8; a++)
#pragma unroll
        for (int c = 0; c < 4; c++) acc[a][c] = 0.f;

    for (int c0 = 0; c0 < CIN; c0 += CK) {
        // input tile (coalesced along t)
        for (int i = tid; i < CK * WROW; i += 256) {
            int idx = i % WROW, ci = i / WROW;
            int t = t0 + idx - HALO;
            float v = 0.f;
            if (t >= 0 && t < TDIM) v = in[(b * CIN + c0 + ci) * TDIM + t];
            sIn[ci][idx] = v;
        }
        // weight tile (coalesced along co thanks to repack)
        for (int i = tid; i < CK * KS * CT; i += 256) {
            int co = i % CT, rk = i / CT;
            sW[rk][co] = wT[(c0 * KS + rk) * COUT + co0 + co];
        }
        __syncthreads();

#pragma unroll 4
        for (int ci = 0; ci < CK; ci++) {
#pragma unroll
            for (int k = 0; k < KS; k++) {
                float iv[4], wv[8];
#pragma unroll
                for (int jt = 0; jt < 4; jt++) iv[jt] = sIn[ci][tx + 32 * jt + k * DIL];
#pragma unroll
                for (int jc = 0; jc < 8; jc++) wv[jc] = sW[ci * KS + k][ty + 8 * jc];
#pragma unroll
                for (int jc = 0; jc < 8; jc++)
#pragma unroll
                    for (int jt = 0; jt < 4; jt++) acc[jc][jt] += wv[jc] * iv[jt];
            }
        }
        __syncthreads();
    }

#pragma unroll
    for (int jc = 0; jc < 8; jc++) {
        int co = co0 + ty + 8 * jc;
        float bb = bias[co];
#pragma unroll
        for (int jt = 0; jt < 4; jt++) {
            int t = t0 + tx + 32 * jt;
            float v = acc[jc][jt] + bb;
            if (RES) v += res[(b * COUT + co) * TDIM + t];
            out[(b * COUT + co) * TDIM + t] = v;
        }
    }
}

// ---------------- transpose [B,C,T] -> [B,T,C] ----------------
__global__ void transpose_kernel(const float* __restrict__ in, float* __restrict__ out, int C) {
    __shared__ float tile[32][33];
    int b = blockIdx.z;
    int t0 = blockIdx.x * 32, c0 = blockIdx.y * 32;
    int tx = threadIdx.x, ty = threadIdx.y;  // 32 x 8
#pragma unroll
    for (int i = 0; i < 32; i += 8)
        tile[ty + i][tx] = in[(b * C + c0 + ty + i) * TDIM + t0 + tx];
    __syncthreads();
#pragma unroll
    for (int i = 0; i < 32; i += 8)
        out[(b * TDIM + t0 + ty + i) * C + c0 + tx] = tile[tx][ty + i];
}

// ---------------- fused dense head: relu(X@W1+b1)@W2+b2 -> [M,12] ----------------
__global__ __launch_bounds__(256) void dense_interp_kernel(
    const float* __restrict__ X,    // [M,320]
    const float* __restrict__ W1,   // [320,1280]
    const float* __restrict__ b1,   // [1280]
    const float* __restrict__ W2,   // [1280,12]
    const float* __restrict__ b2,   // [12]
    float* __restrict__ out)        // [M,12]
{
    __shared__ float sX[16][65];
    __shared__ float sW1[16][128];
    __shared__ float sH[64][129];

    int row0 = blockIdx.x * 64;
    int tid = threadIdx.x;
    int tx = tid & 31, ty = tid >> 5;

    float yacc[3] = {0.f, 0.f, 0.f};

    for (int ch = 0; ch < 10; ch++) {
        float acc[8][4];
#pragma unroll
        for (int a = 0; a < 8; a++)
#pragma unroll
            for (int c = 0; c < 4; c++) acc[a][c] = 0.f;

        for (int kt = 0; kt < 20; kt++) {
            for (int i = tid; i < 16 * 64; i += 256) {
                int kk = i & 15, r = i >> 4;
                sX[kk][r] = X[(row0 + r) * 320 + kt * 16 + kk];
            }
            for (int i = tid; i < 16 * 128; i += 256) {
                int c = i & 127, kk = i >> 7;
                sW1[kk][c] = W1[(kt * 16 + kk) * 1280 + ch * 128 + c];
            }
            __syncthreads();
#pragma unroll 4
            for (int kk = 0; kk < 16; kk++) {
                float xv[8], wv[4];
#pragma unroll
                for (int jr = 0; jr < 8; jr++) xv[jr] = sX[kk][ty + 8 * jr];
#pragma unroll
                for (int jc = 0; jc < 4; jc++) wv[jc] = sW1[kk][tx + 32 * jc];
#pragma unroll
                for (int jr = 0; jr < 8; jr++)
#pragma unroll
                    for (int jc = 0; jc < 4; jc++) acc[jr][jc] += xv[jr] * wv[jc];
            }
            __syncthreads();
        }
        // relu(h + b1) -> sH
#pragma unroll
        for (int jc = 0; jc < 4; jc++) {
            float bb = b1[ch * 128 + tx + 32 * jc];
#pragma unroll
            for (int jr = 0; jr < 8; jr++) {
                float v = acc[jr][jc] + bb;
                sH[ty + 8 * jr][tx + 32 * jc] = v > 0.f ? v : 0.f;
            }
        }
        __syncthreads();
        // stage2: y[64][12] accumulate, 3 pairs/thread
#pragma unroll
        for (int q = 0; q < 3; q++) {
            int p = tid + 256 * q;
            int r = p / 12, o = p % 12;
            float s = 0.f;
#pragma unroll 8
            for (int k = 0; k < 128; k++) s += sH[r][k] * W2[(ch * 128 + k) * 12 + o];
            yacc[q] += s;
        }
        __syncthreads();
    }
#pragma unroll
    for (int q = 0; q < 3; q++) {
        int p = tid + 256 * q;
        int r = p / 12, o = p % 12;
        out[(row0 + r) * 12 + o] = yacc[q] + b2[o];
    }
}

// outputs1 = outputs2 = interp @ M12 + c12
__global__ void outputs_kernel(const float* __restrict__ interp,
                               const float* __restrict__ M12, const float* __restrict__ c12,
                               float* __restrict__ o1, float* __restrict__ o2) {
    int r = blockIdx.x * blockDim.x + threadIdx.x;
    if (r >= BT) return;
    float xv[12];
#pragma unroll
    for (int i = 0; i < 12; i++) xv[i] = interp[r * 12 + i];
#pragma unroll
    for (int j = 0; j < 12; j++) {
        float s = c12[j];
#pragma unroll
        for (int i = 0; i < 12; i++) s += xv[i] * M12[i * 12 + j];
        o1[r * 12 + j] = s;
        o2[r * 12 + j] = s;
    }
}

// masks + passthrough copies
__global__ void tail_kernel(const float* __restrict__ x1, const float* __restrict__ x2,
                            float* __restrict__ om1, float* __restrict__ om2,
                            float* __restrict__ ox1, float* __restrict__ ox2) {
    int i = blockIdx.x * blockDim.x + threadIdx.x;
    if (i < BT * DIN) {
        float a = x1[i], b = x2[i];
        om1[i] = (a != 0.f) ? 1.f : 0.f;
        om2[i] = (b != 0.f) ? 1.f : 0.f;
        ox1[i] = a;
        ox2[i] = b;
    }
}

// ---------------- host side ----------------
struct ConvW { const float *c01b, *c02b, *c1pb, *c11b, *c12b; };

static void run_encoder(const float* in, const float* w_in, const float* b_in,
                        const ConvW& cb,
                        float* wc01, float* wc02, float* wc1p, float* wc11, float* wc12,
                        float* b64a, float* b64b, float* b64c,
                        float* b320a, float* b320b, float* b320c) {
    const int n64_4 = (BB * HH * TDIM) / 4;
    const int n320_4 = (BB * DOUT * TDIM) / 4;
    dim3 g64(TDIM / 128, 1, BB), g320(TDIM / 128, DOUT / 64, BB);

    proj_in_kernel<<<dim3(TDIM / 128, BB), 128>>>(in, w_in, b_in, b64a);
    gelu4_kernel<<<(n64_4 + 255) / 256, 256>>>((const float4*)b64a, (float4*)b64b, n64_4);
    conv_kernel<HH, HH, 3, 1, false><<<g64, 256>>>(b64b, wc01, cb.c01b, nullptr, b64c);
    gelu4_kernel<<<(n64_4 + 255) / 256, 256>>>((const float4*)b64c, (float4*)b64b, n64_4);
    conv_kernel<HH, HH, 3, 1, true><<<g64, 256>>>(b64b, wc02, cb.c02b, b64a, b64c);
    // block1: h = b64c
    conv_kernel<HH, DOUT, 1, 1, false><<<g320, 256>>>(b64c, wc1p, cb.c1pb, nullptr, b320a);
    gelu4_kernel<<<(n64_4 + 255) / 256, 256>>>((const float4*)b64c, (float4*)b64b, n64_4);
    conv_kernel<HH, DOUT, 3, 2, false><<<g320, 256>>>(b64b, wc11, cb.c11b, nullptr, b320b);
    gelu4_kernel<<<(n320_4 + 255) / 256, 256>>>((const float4*)b320b, (float4*)b320c, n320_4);
    conv_kernel<DOUT, DOUT, 3, 2, true><<<g320, 256>>>(b320c, wc12, cb.c12b, b320a, b320b);
    // result in b320b  [B,320,T]
}

extern "C" void kernel_launch(void* const* d_in, const int* in_sizes, int n_in,
                              void* d_out, int out_size) {
    const float* x1 = (const float*)d_in[0];
    const float* x2 = (const float*)d_in[1];
    const float* X1 = (const float*)d_in[2];
    const float* X2 = (const float*)d_in[3];
    const float* w_in = (const float*)d_in[5];
    const float* b_in = (const float*)d_in[6];
    const float* c0_1_w = (const float*)d_in[7];
    const float* c0_1_b = (const float*)d_in[8];
    const float* c0_2_w = (const float*)d_in[9];
    const float* c0_2_b = (const float*)d_in[10];
    const float* c1_p_w = (const float*)d_in[11];
    const float* c1_p_b = (const float*)d_in[12];
    const float* c1_1_w = (const float*)d_in[13];
    const float* c1_1_b = (const float*)d_in[14];
    const float* c1_2_w = (const float*)d_in[15];
    const float* c1_2_b = (const float*)d_in[16];
    const float* ih_dense_w = (const float*)d_in[17];
    const float* ih_dense_b = (const float*)d_in[18];
    const float* ih_proj_w = (const float*)d_in[19];
    const float* ih_proj_b = (const float*)d_in[20];
    const float* fc_w = (const float*)d_in[21];
    const float* fc_b = (const float*)d_in[22];
    const float* fcr_w = (const float*)d_in[29];
    const float* fcr_b = (const float*)d_in[30];

    float *b64a, *b64b, *b64c, *b320a, *b320b, *b320c, *interp;
    float *wc01, *wc02, *wc1p, *wc11, *wc12, *M12, *c12;
    cudaGetSymbolAddress((void**)&b64a, g_b64_a);
    cudaGetSymbolAddress((void**)&b64b, g_b64_b);
    cudaGetSymbolAddress((void**)&b64c, g_b64_c);
    cudaGetSymbolAddress((void**)&b320a, g_b320_a);
    cudaGetSymbolAddress((void**)&b320b, g_b320_b);
    cudaGetSymbolAddress((void**)&b320c, g_b320_c);
    cudaGetSymbolAddress((void**)&interp, g_interp);
    cudaGetSymbolAddress((void**)&wc01, g_wT_c01);
    cudaGetSymbolAddress((void**)&wc02, g_wT_c02);
    cudaGetSymbolAddress((void**)&wc1p, g_wT_c1p);
    cudaGetSymbolAddress((void**)&wc11, g_wT_c11);
    cudaGetSymbolAddress((void**)&wc12, g_wT_c12);
    cudaGetSymbolAddress((void**)&M12, g_M12);
    cudaGetSymbolAddress((void**)&c12, g_c12);

    // weight repacks + fused 12x12 head matrix
    repack_w_kernel<<<48, 256>>>(c0_1_w, wc01, HH, HH, 3);
    repack_w_kernel<<<48, 256>>>(c0_2_w, wc02, HH, HH, 3);
    repack_w_kernel<<<80, 256>>>(c1_p_w, wc1p, DOUT, HH, 1);
    repack_w_kernel<<<240, 256>>>(c1_1_w, wc11, DOUT, HH, 3);
    repack_w_kernel<<<1200, 256>>>(c1_2_w, wc12, DOUT, DOUT, 3);
    m12_kernel<<<1, 256>>>(fc_w, fc_b, fcr_w, fcr_b, M12, c12);

    float* out = (float*)d_out;
    float* o_xw1 = out;
    float* o_xw2 = out + (size_t)BT * DOUT;
    float* o_o1  = out + 2 * (size_t)BT * DOUT;
    float* o_o2  = o_o1 + (size_t)BT * DIN;
    float* o_m1  = o_o2 + (size_t)BT * DIN;
    float* o_m2  = o_m1 + (size_t)BT * DIN;
    float* o_x1  = o_m2 + (size_t)BT * DIN;
    float* o_x2  = o_x1 + (size_t)BT * DIN;

    ConvW cb{c0_1_b, c0_2_b, c1_p_b, c1_1_b, c1_2_b};
    dim3 tgrid(TDIM / 32, DOUT / 32, BB), tblk(32, 8);

    // x_whole1 = enc(X1)
    run_encoder(X1, w_in, b_in, cb, wc01, wc02, wc1p, wc11, wc12,
                b64a, b64b, b64c, b320a, b320b, b320c);
    transpose_kernel<<<tgrid, tblk>>>(b320b, o_xw1, DOUT);

    // x_whole2 = enc(X2)
    run_encoder(X2, w_in, b_in, cb, wc01, wc02, wc1p, wc11, wc12,
                b64a, b64b, b64c, b320a, b320b, b320c);
    transpose_kernel<<<tgrid, tblk>>>(b320b, o_xw2, DOUT);

    // interp path on x1 (x2's interp path and the GRU are provably dead)
    run_encoder(x1, w_in, b_in, cb, wc01, wc02, wc1p, wc11, wc12,
                b64a, b64b, b64c, b320a, b320b, b320c);
    transpose_kernel<<<tgrid, tblk>>>(b320b, b320c, DOUT);  // [B*T,320]
    dense_interp_kernel<<<BT / 64, 256>>>(b320c, ih_dense_w, ih_dense_b,
                                          ih_proj_w, ih_proj_b, interp);
    outputs_kernel<<<(BT + 127) / 128, 128>>>(interp, M12, c12, o_o1, o_o2);
    tail_kernel<<<(BT * DIN + 255) / 256, 256>>>(x1, x2, o_m1, o_m2, o_x1, o_x2);
}